// round 14
// baseline (speedup 1.0000x reference)
#include <cuda_runtime.h>
#include <cuda_bf16.h>
#include <cstdint>

// Problem constants (fixed by setup_inputs):
//   encoder_output: (B=32, L_ENC=512, E=256) float32
//   durations:      (B=32, L_ENC=512) int32, values in [0, 8)
//   output:         (B=32, L_DEC=2048, E=256) float32
//
// out[b, d, :] = enc[b, l, :] where cs[l-1] <= d < cs[l]; 0 for d >= cs[511].

#define B_SZ    32
#define L_ENC   512
#define L_DEC   2048
#define E_DIM   256
#define E_VEC   (E_DIM / 4)            // 64 float4 per row
#define TILE_ROWS 32                   // decoder rows per block
#define TILE_VEC  (TILE_ROWS * E_VEC)  // 2048 float4 = 32 KB
#define TILE_BYTES (TILE_ROWS * E_DIM * 4)          // 32768
#define BLOCKS_PER_BATCH (L_DEC / TILE_ROWS)        // 64
#define N_BLOCKS (B_SZ * BLOCKS_PER_BATCH)          // 2048

__device__ __forceinline__ uint32_t smem_u32(const void* p)
{
    uint32_t a;
    asm("{ .reg .u64 t; cvta.to.shared.u64 t, %1; cvt.u32.u64 %0, t; }"
        : "=r"(a) : "l"(p));
    return a;
}

// ---------------------------------------------------------------------------
// Single fused kernel. Grid = 2048 blocks, 512 threads.
// Per block (32 consecutive decoder rows of one batch):
//  1. in-block scan of the batch's 512 durations (L2-hot, warp shuffles)
//  2. s_map[32]: decoder row -> enc row (-1 = padding)
//  3. stage the 32 KB output tile in smem: 4 float4/thread
//     (LDG from enc or zero; STS ~4cyc vs STG.128 ~12cyc LSU issue)
//  4. ONE cp.async.bulk 32 KB smem -> gmem (contiguous rows) via async engine
// ---------------------------------------------------------------------------
__global__ void __launch_bounds__(512)
lr_fused_kernel(const float4* __restrict__ enc,
                const int*    __restrict__ dur,
                float4* __restrict__ out)
{
    __shared__ float4 s_tile[TILE_VEC];      // 32 KB staged output tile
    __shared__ int    s_map[TILE_ROWS];
    __shared__ int    s_wsum[16];

    const int bid  = blockIdx.x;
    const int b    = bid >> 6;               // batch (64 blocks per batch)
    const int blk  = bid & 63;               // tile within batch
    const int base = blk * TILE_ROWS;        // decoder row base
    const int t    = threadIdx.x;
    const int wid  = t >> 5;
    const int lane = t & 31;

    // ---- 1. block-wide inclusive scan of this batch's 512 durations ----
    const int my_dur = dur[b * L_ENC + t];
    int v = my_dur;
    #pragma unroll
    for (int off = 1; off < 32; off <<= 1) {
        int u = __shfl_up_sync(0xffffffffu, v, off);
        if (lane >= off) v += u;
    }
    if (lane == 31) s_wsum[wid] = v;
    if (t < TILE_ROWS) s_map[t] = -1;
    __syncthreads();

    if (wid == 0 && lane < 16) {
        int ws = s_wsum[lane];
        #pragma unroll
        for (int off = 1; off < 16; off <<= 1) {
            int u = __shfl_up_sync(0x0000ffffu, ws, off);
            if (lane >= off) ws += u;
        }
        s_wsum[lane] = ws - s_wsum[lane];     // exclusive prefix of warp sums
    }
    __syncthreads();

    const int incl = v + s_wsum[wid];         // inclusive cumsum at enc row t
    const int excl = incl - my_dur;

    // ---- 2. scatter map: enc row t covers decoder rows [excl, incl) ----
    {
        int lo = excl > base ? excl : base;
        int hi = incl < base + TILE_ROWS ? incl : base + TILE_ROWS;
        for (int d = lo; d < hi; ++d)
            s_map[d - base] = t;
    }
    __syncthreads();

    // ---- 3. stage tile: 4 float4 per thread ----
    const float4* enc_b = enc + ((long)b * L_ENC) * E_VEC;
    #pragma unroll
    for (int k = 0; k < 4; ++k) {
        const int i    = t + k * 512;         // 0..2047
        const int row  = i >> 6;
        const int ln   = i & 63;
        const int src  = s_map[row];          // broadcast LDS
        float4 vv;
        if (src >= 0)
            vv = __ldg(enc_b + (long)src * E_VEC + ln);
        else
            vv = make_float4(0.f, 0.f, 0.f, 0.f);
        s_tile[i] = vv;
    }
    __syncthreads();

    // ---- 4. one 32 KB bulk store, async proxy ----
    asm volatile("fence.proxy.async.shared::cta;" ::: "memory");
    if (t == 0) {
        float4* gdst = out + ((long)(b * L_DEC + base)) * E_VEC;
        const uint32_t ssrc = smem_u32(&s_tile[0]);
        asm volatile(
            "cp.async.bulk.global.shared::cta.bulk_group [%0], [%1], %2;"
            :: "l"(gdst), "r"(ssrc), "n"(TILE_BYTES) : "memory");
        asm volatile("cp.async.bulk.commit_group;" ::: "memory");
        asm volatile("cp.async.bulk.wait_group.read 0;" ::: "memory");
    }
    __syncthreads();   // smem must stay live until TMA reads complete
}

// ---------------------------------------------------------------------------
extern "C" void kernel_launch(void* const* d_in, const int* in_sizes, int n_in,
                              void* d_out, int out_size)
{
    const float* enc = (const float*)d_in[0];     // (B, L_ENC, E)
    const int*   dur = (const int*)d_in[1];       // (B, L_ENC) int32
    (void)in_sizes; (void)n_in; (void)out_size;

    lr_fused_kernel<<<N_BLOCKS, 512>>>((const float4*)enc, dur,
                                       (float4*)d_out);
}